// round 10
// baseline (speedup 1.0000x reference)
#include <cuda_runtime.h>
#include <cuda_bf16.h>
#include <cstdint>

#define N_NODES 207
#define N_EDGES 1722
#define N_SLOTS 288
#define LDIM    64
#define BATCH   1024
#define N_SLOTS_PAD 256          // 4 passes * 16 warps * 4 slots
#define ADJ_CAP 5120             // >= 16 * sum_quads(max ng)
#define PACK_STRIDE (ADJ_CAP + 4) // +4 u32 pad so prefetch over-read is safe

// ---------------- device-global scratch (no allocs allowed) ----------------
__device__ int g_deg[N_NODES];                               // exact degree per node
__device__ int g_nodebase[N_NODES];                          // entry base per node
__device__ int g_rowptr4[N_SLOTS_PAD + 1];                   // entry start per SORTED SLOT
__device__ unsigned short g_order[N_SLOTS_PAD];              // slot -> node id (0xFFFF invalid)
__device__ __align__(16) unsigned short g_adj_node[ADJ_CAP]; // nbr*128 (byte offset of bf16 row)
__device__ __align__(16) unsigned short g_adj_edge[ADJ_CAP]; // edge idx; N_EDGES = dummy (w=0)
// per-slot precomputed tables (slot-only data hoisted out of the main kernel)
__device__ __align__(16) unsigned g_packed[N_SLOTS][PACK_STRIDE]; // (bf16 w)<<16 | byteoff
__device__ float g_sc[N_SLOTS][208];                              // deg + 1 + wsl per node

// ---------------- setup 1a: parallel degree count + dummy fill -------------
// Blocks 0..206: block v counts its own degree (order-independent, no atomics).
// Blocks 207..255: dummy-fill g_adj (overwritten where real entries land).
__global__ __launch_bounds__(128, 8)
void count_deg_kernel(const int* __restrict__ edge_i,
                      const int* __restrict__ edge_j) {
    const int bid = blockIdx.x;
    const int tid = threadIdx.x;

    if (bid >= N_NODES) {
        const int t = (bid - N_NODES) * 128 + tid;
        if (t < ADJ_CAP) {
            g_adj_node[t] = 0;
            g_adj_edge[t] = (unsigned short)N_EDGES;   // dummy -> weight 0
        }
        return;
    }

    const int v = bid;
    int cnt = 0;
    for (int idx = tid; idx < 2 * N_EDGES; idx += 128) {
        const int e  = idx >> 1;
        const int vi = (idx & 1) ? __ldg(edge_j + e) : __ldg(edge_i + e);
        cnt += (vi == v);
    }
    #pragma unroll
    for (int o = 16; o; o >>= 1) cnt += __shfl_down_sync(0xffffffffu, cnt, o);
    __shared__ int sc[4];
    if ((tid & 31) == 0) sc[tid >> 5] = cnt;
    __syncthreads();
    if (tid == 0) g_deg[v] = sc[0] + sc[1] + sc[2] + sc[3];
}

// ---------------- setup 1b: sort + quad-padded rowptr (tiny, 1 block) ------
__global__ __launch_bounds__(256, 1)
void sort_scan_kernel() {
    __shared__ int s_ng[N_NODES];
    __shared__ unsigned short s_ord[N_SLOTS_PAD];
    const int tid  = threadIdx.x;
    const int lane = tid & 31;

    if (tid < N_NODES) s_ng[tid] = (g_deg[tid] + 3) >> 2;
    if (tid < N_SLOTS_PAD) s_ord[tid] = 0xFFFFu;
    __syncthreads();

    // parallel rank sort: desc by ng, tie asc id
    if (tid < N_NODES) {
        const int nv = s_ng[tid];
        int r = 0;
        for (int u = 0; u < N_NODES; ++u) {
            const int nu = s_ng[u];
            r += (nu > nv) || (nu == nv && u < tid);
        }
        s_ord[r] = (unsigned short)tid;
    }
    __syncthreads();

    // quad scan: 64 quads, 2 rounds of 32 (warp 0)
    if (tid < 32) {
        int carryG = 0;                       // in "quad-max groups"
        #pragma unroll
        for (int c = 0; c < 2; ++c) {
            const int q = c * 32 + lane;
            const int a0 = s_ord[4 * q + 0], a1 = s_ord[4 * q + 1];
            const int a2 = s_ord[4 * q + 2], a3 = s_ord[4 * q + 3];
            const int n0 = (a0 != 0xFFFF) ? s_ng[a0] : 0;
            const int n1 = (a1 != 0xFFFF) ? s_ng[a1] : 0;
            const int n2 = (a2 != 0xFFFF) ? s_ng[a2] : 0;
            const int n3 = (a3 != 0xFFFF) ? s_ng[a3] : 0;
            int m = n0 > n1 ? n0 : n1;
            m = m > n2 ? m : n2;
            m = m > n3 ? m : n3;
            int si = m;
            #pragma unroll
            for (int o = 1; o < 32; o <<= 1) {
                const int t = __shfl_up_sync(0xffffffffu, si, o);
                if (lane >= o) si += t;
            }
            const int base = (carryG + si - m) * 16;   // entries
            g_rowptr4[4 * q + 0] = base;
            g_rowptr4[4 * q + 1] = base + 4 * m;
            g_rowptr4[4 * q + 2] = base + 8 * m;
            g_rowptr4[4 * q + 3] = base + 12 * m;
            if (a0 != 0xFFFF) g_nodebase[a0] = base;
            if (a1 != 0xFFFF) g_nodebase[a1] = base + 4 * m;
            if (a2 != 0xFFFF) g_nodebase[a2] = base + 8 * m;
            if (a3 != 0xFFFF) g_nodebase[a3] = base + 12 * m;
            carryG += __shfl_sync(0xffffffffu, si, 31);
        }
        if (lane == 0) g_rowptr4[N_SLOTS_PAD] = carryG * 16;
    }
    __syncthreads();
    for (int i = tid; i < N_SLOTS_PAD; i += 256) g_order[i] = s_ord[i];
}

// ---------------- setup 1c: parallel deterministic scatter -----------------
// One WARP per node; streams all entries in 108 ballot rounds. Rank =
// (round order, lane order) == ascending entry index -> identical ordering
// to the old single-block scatter. No atomics, no block barriers.
__global__ __launch_bounds__(32, 16)
void scatter_kernel(const int* __restrict__ edge_i,
                    const int* __restrict__ edge_j) {
    const int v    = blockIdx.x;
    const int lane = threadIdx.x;
    int run = g_nodebase[v];

    #pragma unroll 4
    for (int c = 0; c < (2 * N_EDGES + 31) / 32; ++c) {
        const int idx = c * 32 + lane;
        int vi = -1, nbr = 0, e = 0;
        if (idx < 2 * N_EDGES) {
            e = idx >> 1;
            const int a = __ldg(edge_i + e);
            const int b = __ldg(edge_j + e);
            vi  = (idx & 1) ? b : a;
            nbr = (idx & 1) ? a : b;
        }
        const bool m = (vi == v);
        const unsigned bal = __ballot_sync(0xffffffffu, m);
        if (m) {
            const int pos = run + __popc(bal & ((1u << lane) - 1u));
            g_adj_node[pos] = (unsigned short)(nbr * 128);   // byte offset of row
            g_adj_edge[pos] = (unsigned short)e;
        }
        run += __popc(bal);
    }
}

// ---------------- setup 2: per-slot packed meta + scale table --------------
__global__ __launch_bounds__(512, 2)
void pack_meta_kernel(const float* __restrict__ weight_diff,   // (S,E)
                      const float* __restrict__ weight_sl) {   // (S,N)
    __shared__ float s_w[1728];
    const int s   = blockIdx.x;
    const int tid = threadIdx.x;
    const float* wrow = weight_diff + (size_t)s * N_EDGES;

    for (int i = tid; i < 1728; i += 512)
        s_w[i] = (i < N_EDGES) ? wrow[i] : 0.0f;
    __syncthreads();

    for (int t = tid; t < ADJ_CAP; t += 512) {
        const float w = s_w[(int)g_adj_edge[t]];
        const unsigned wb = (unsigned)__bfloat16_as_ushort(__float2bfloat16(w));
        g_packed[s][t] = (wb << 16) | (unsigned)g_adj_node[t];
    }
    if (tid < 4) g_packed[s][ADJ_CAP + tid] = 0;   // prefetch pad

    if (tid < N_SLOTS_PAD) {
        const int w = g_order[tid];
        if (w != 0xFFFF) {
            const int beg = g_rowptr4[tid];
            const int end = g_rowptr4[tid + 1];
            float deg = 0.0f;
            for (int t = beg; t < end; ++t)
                deg += s_w[(int)g_adj_edge[t]];     // dummies add 0
            g_sc[s][w] = deg + 1.0f + weight_sl[(size_t)s * N_NODES + w];
        }
    }
}

// ---------------- main kernel: one CTA (512 thr) per batch (R9, unchanged) -
#define SMEM_BYTES 26496

__device__ __forceinline__ __nv_bfloat162 as_bf2(unsigned v) {
    return *reinterpret_cast<__nv_bfloat162*>(&v);
}
__device__ __forceinline__ unsigned as_u32(__nv_bfloat162 v) {
    return *reinterpret_cast<unsigned*>(&v);
}

#define ENTRY(PK) do {                                                \
    const uint4 u = *(const uint4*)(sxb + ((PK) & 0xffffu));          \
    const __nv_bfloat162 wb = as_bf2(__byte_perm((PK), (PK), 0x3232));\
    c0 = __hfma2(wb, as_bf2(u.x), c0);                                \
    c1 = __hfma2(wb, as_bf2(u.y), c1);                                \
    c2 = __hfma2(wb, as_bf2(u.z), c2);                                \
    c3 = __hfma2(wb, as_bf2(u.w), c3);                                \
} while (0)

__global__ __launch_bounds__(512, 4)
void diffusion_gcn_kernel(const float*  __restrict__ inputs,      // (B,2,N,L)
                          const float*  __restrict__ bias_diff,   // (S,N)
                          const int*    __restrict__ ind,         // (B,)
                          float*        __restrict__ out)         // (B,N,L)
{
    extern __shared__ char smem[];
    unsigned* s_xu = (unsigned*)smem;                 // bf16 tile, 32 u32/row

    const int b    = blockIdx.x;
    const int tid  = threadIdx.x;
    const int slot = ind[b];
    const float* __restrict__ xg = inputs + (size_t)b * 2 * N_NODES * LDIM;

    {   // stage x -> bf16 tile (only smem staging; one barrier total)
        const float4* src = (const float4*)xg;
        uint2* dst = (uint2*)s_xu;
        #pragma unroll 4
        for (int i = tid; i < (N_NODES * LDIM) / 4; i += 512) {
            const float4 v = src[i];
            uint2 p;
            p.x = as_u32(__floats2bfloat162_rn(v.x, v.y));
            p.y = as_u32(__floats2bfloat162_rn(v.z, v.w));
            dst[i] = p;
        }
    }
    __syncthreads();

    const int warp    = tid >> 5;        // 0..15
    const int lane    = tid & 31;
    const int quarter = lane >> 3;       // slot within quad
    const int hl      = lane & 7;        // 8-column group within slot
    const char* sxb   = (const char*)s_xu + 16 * hl;
    const unsigned* prow  = &g_packed[slot][0];
    const float*    scrow = &g_sc[slot][0];
    const float*    birow = bias_diff + (size_t)slot * N_NODES;

    #pragma unroll 1
    for (int pass = 0; pass < 4; ++pass) {
        const int sl  = pass * 64 + warp * 4 + quarter;
        const int w   = (int)__ldg(&g_order[sl]);
        const int beg = __ldg(&g_rowptr4[sl]);
        const int ng  = (__ldg(&g_rowptr4[sl + 1]) - beg) >> 2;  // uniform in quad

        const uint4* mp = (const uint4*)(prow + beg);
        uint4 p = __ldg(mp);                                      // group 0

        const float* xr = (w != 0xFFFF) ? (xg + w * LDIM + 8 * hl) : xg;
        const float4 x0 = *(const float4*)xr;

        __nv_bfloat162 c0 = as_bf2(0u), c1 = as_bf2(0u);
        __nv_bfloat162 c2 = as_bf2(0u), c3 = as_bf2(0u);

        #pragma unroll 1
        for (int g = 0; g < ng; ++g) {
            const uint4 pn = __ldg(mp + g + 1);   // padded over-read is safe
            ENTRY(p.x);
            ENTRY(p.y);
            ENTRY(p.z);
            ENTRY(p.w);
            p = pn;
        }

        if (w != 0xFFFF) {
            const float4 x1 = *(const float4*)(xr + 4);
            const float sc = __ldg(scrow + w);
            const float bi = __ldg(birow + w);
            const unsigned r0 = as_u32(c0), r1 = as_u32(c1);
            const unsigned r2 = as_u32(c2), r3 = as_u32(c3);
            float4 o0, o1;
            o0.x = fmaf(sc, x0.x, bi - __uint_as_float(r0 << 16));
            o0.y = fmaf(sc, x0.y, bi - __uint_as_float(r0 & 0xffff0000u));
            o0.z = fmaf(sc, x0.z, bi - __uint_as_float(r1 << 16));
            o0.w = fmaf(sc, x0.w, bi - __uint_as_float(r1 & 0xffff0000u));
            o1.x = fmaf(sc, x1.x, bi - __uint_as_float(r2 << 16));
            o1.y = fmaf(sc, x1.y, bi - __uint_as_float(r2 & 0xffff0000u));
            o1.z = fmaf(sc, x1.z, bi - __uint_as_float(r3 << 16));
            o1.w = fmaf(sc, x1.w, bi - __uint_as_float(r3 & 0xffff0000u));
            float* op = out + ((size_t)b * N_NODES + w) * LDIM + 8 * hl;
            *(float4*)op = o0;
            *(float4*)(op + 4) = o1;
        }
    }
}

// ---------------- launcher ---------------------------------------------
extern "C" void kernel_launch(void* const* d_in, const int* in_sizes, int n_in,
                              void* d_out, int out_size) {
    const float* inputs      = (const float*)d_in[0];
    const float* weight_diff = (const float*)d_in[1];
    const float* bias_diff   = (const float*)d_in[2];
    const float* weight_sl   = (const float*)d_in[3];
    const int*   ind         = (const int*)d_in[4];
    const int*   edge_i      = (const int*)d_in[5];
    const int*   edge_j      = (const int*)d_in[6];
    float*       out         = (float*)d_out;

    static bool attr_set = false;   // host-side config only, not a work guard
    if (!attr_set) {
        cudaFuncSetAttribute(diffusion_gcn_kernel,
                             cudaFuncAttributeMaxDynamicSharedMemorySize,
                             SMEM_BYTES);
        attr_set = true;
    }

    count_deg_kernel<<<256, 128>>>(edge_i, edge_j);
    sort_scan_kernel<<<1, 256>>>();
    scatter_kernel<<<N_NODES, 32>>>(edge_i, edge_j);
    pack_meta_kernel<<<N_SLOTS, 512>>>(weight_diff, weight_sl);
    diffusion_gcn_kernel<<<BATCH, 512, SMEM_BYTES>>>(
        inputs, bias_diff, ind, out);
}

// round 11
// speedup vs baseline: 1.0974x; 1.0974x over previous
#include <cuda_runtime.h>
#include <cuda_bf16.h>
#include <cstdint>

#define N_NODES 207
#define N_EDGES 1722
#define N_SLOTS 288
#define LDIM    64
#define BATCH   1024
#define N_SLOTS_PAD 256          // 4 passes * 16 warps * 4 slots
#define ADJ_CAP 5120             // >= 16 * sum_quads(max ng)
#define PACK_PAD 5128            // +8 u32 pad (uint4-copyable, prefetch-safe)

// ---------------- device-global scratch (no allocs allowed) ----------------
__device__ int g_rowptr4[N_SLOTS_PAD + 1];                   // entry start per SORTED SLOT
__device__ unsigned short g_order[N_SLOTS_PAD];              // slot -> node id (0xFFFF invalid)
__device__ __align__(16) unsigned short g_adj_node[ADJ_CAP]; // nbr*128 (byte offset of bf16 row)
__device__ __align__(16) unsigned short g_adj_edge[ADJ_CAP]; // edge idx; N_EDGES = dummy (w=0)
// per-slot precomputed tables (slot-only work done once per launch, not 1024x)
__device__ __align__(16) unsigned g_packed[N_SLOTS][PACK_PAD]; // (bf16 w)<<16 | byteoff
__device__ float g_sc[N_SLOTS][208];                           // deg + 1 + wsl per node

// ---------------- setup 1: deterministic quad-padded sorted CSR ------------
// (proven single-block builder from rounds 6/8 — warm cost ~5-7 us)
__global__ __launch_bounds__(1024, 1)
void build_csr_kernel(const int* __restrict__ edge_i,
                      const int* __restrict__ edge_j) {
    __shared__ int s_ei[N_EDGES];
    __shared__ int s_ej[N_EDGES];
    __shared__ int s_ng[N_NODES];
    __shared__ int s_off[N_NODES + 1];          // deg count -> slot entry base
    __shared__ unsigned short s_ord[N_SLOTS_PAD];
    __shared__ int s_wcnt[32][208];
    const int tid  = threadIdx.x;
    const int warp = tid >> 5;
    const int lane = tid & 31;

    for (int i = tid; i < N_EDGES; i += 1024) {
        s_ei[i] = edge_i[i];
        s_ej[i] = edge_j[i];
    }
    for (int v = tid; v < N_NODES + 1; v += 1024) s_off[v] = 0;
    for (int i = tid; i < N_SLOTS_PAD; i += 1024) s_ord[i] = 0xFFFFu;
    for (int t = tid; t < ADJ_CAP; t += 1024) {
        g_adj_node[t] = 0;
        g_adj_edge[t] = (unsigned short)N_EDGES;    // dummy -> weight 0
    }
    for (int i = tid; i < 32 * 208; i += 1024) ((int*)s_wcnt)[i] = 0;
    __syncthreads();

    for (int idx = tid; idx < 2 * N_EDGES; idx += 1024) {
        const int e = idx >> 1;
        atomicAdd(&s_off[(idx & 1) ? s_ej[e] : s_ei[e]], 1);
    }
    __syncthreads();

    if (tid < N_NODES) s_ng[tid] = (s_off[tid] + 3) >> 2;
    __syncthreads();

    // parallel rank sort: desc by ng, tie asc id
    if (tid < N_NODES) {
        const int nv = s_ng[tid];
        int r = 0;
        for (int u = 0; u < N_NODES; ++u) {
            const int nu = s_ng[u];
            r += (nu > nv) || (nu == nv && u < tid);
        }
        s_ord[r] = (unsigned short)tid;
    }
    __syncthreads();

    // quad scan: 64 quads, 2 rounds of 32 (warp 0)
    if (warp == 0) {
        int carryG = 0;
        #pragma unroll
        for (int c = 0; c < 2; ++c) {
            const int q = c * 32 + lane;
            const int a0 = s_ord[4 * q + 0], a1 = s_ord[4 * q + 1];
            const int a2 = s_ord[4 * q + 2], a3 = s_ord[4 * q + 3];
            const int n0 = (a0 != 0xFFFF) ? s_ng[a0] : 0;
            const int n1 = (a1 != 0xFFFF) ? s_ng[a1] : 0;
            const int n2 = (a2 != 0xFFFF) ? s_ng[a2] : 0;
            const int n3 = (a3 != 0xFFFF) ? s_ng[a3] : 0;
            int m = n0 > n1 ? n0 : n1;
            m = m > n2 ? m : n2;
            m = m > n3 ? m : n3;
            int si = m;
            #pragma unroll
            for (int o = 1; o < 32; o <<= 1) {
                const int t = __shfl_up_sync(0xffffffffu, si, o);
                if (lane >= o) si += t;
            }
            const int base = (carryG + si - m) * 16;   // entries
            g_rowptr4[4 * q + 0] = base;
            g_rowptr4[4 * q + 1] = base + 4 * m;
            g_rowptr4[4 * q + 2] = base + 8 * m;
            g_rowptr4[4 * q + 3] = base + 12 * m;
            if (a0 != 0xFFFF) s_off[a0] = base;
            if (a1 != 0xFFFF) s_off[a1] = base + 4 * m;
            if (a2 != 0xFFFF) s_off[a2] = base + 8 * m;
            if (a3 != 0xFFFF) s_off[a3] = base + 12 * m;
            carryG += __shfl_sync(0xffffffffu, si, 31);
        }
        if (lane == 0) g_rowptr4[N_SLOTS_PAD] = carryG * 16;
    }
    __syncthreads();
    for (int i = tid; i < N_SLOTS_PAD; i += 1024) g_order[i] = s_ord[i];

    // single-chunk deterministic scatter: 4 sequential rounds per lane
    int myrank[4], myv[4], mynbr[4], mye[4];
    #pragma unroll
    for (int r = 0; r < 4; ++r) {
        const int idx = tid * 4 + r;
        const bool valid = idx < 2 * N_EDGES;
        int v = 207, nbr = 0, e = 0;
        if (valid) {
            e = idx >> 1;
            if (idx & 1) { v = s_ej[e]; nbr = s_ei[e]; }
            else         { v = s_ei[e]; nbr = s_ej[e]; }
        }
        const int prefix = s_wcnt[warp][v];
        const unsigned mask = __match_any_sync(0xffffffffu, v);
        const int rin = __popc(mask & ((1u << lane) - 1u));
        myv[r] = v; mynbr[r] = nbr; mye[r] = e;
        myrank[r] = prefix + rin;
        __syncwarp();
        if (lane == (__ffs(mask) - 1)) s_wcnt[warp][v] = prefix + __popc(mask);
        __syncwarp();
    }
    __syncthreads();

    if (tid < 208) {
        int run = (tid < N_NODES) ? s_off[tid] : 0;
        #pragma unroll
        for (int w2 = 0; w2 < 32; ++w2) {
            const int t = s_wcnt[w2][tid];
            s_wcnt[w2][tid] = run;
            run += t;
        }
    }
    __syncthreads();

    #pragma unroll
    for (int r = 0; r < 4; ++r) {
        const int idx = tid * 4 + r;
        if (idx < 2 * N_EDGES) {
            const int pos = s_wcnt[warp][myv[r]] + myrank[r];
            g_adj_node[pos] = (unsigned short)(mynbr[r] * 128);  // byte offset of row
            g_adj_edge[pos] = (unsigned short)mye[r];
        }
    }
}

// ---------------- setup 2: per-slot packed meta + scale table --------------
__global__ __launch_bounds__(512, 2)
void pack_meta_kernel(const float* __restrict__ weight_diff,   // (S,E)
                      const float* __restrict__ weight_sl) {   // (S,N)
    __shared__ float s_w[1728];
    const int s   = blockIdx.x;
    const int tid = threadIdx.x;
    const float* wrow = weight_diff + (size_t)s * N_EDGES;

    for (int i = tid; i < 1728; i += 512)
        s_w[i] = (i < N_EDGES) ? wrow[i] : 0.0f;
    __syncthreads();

    for (int t = tid; t < ADJ_CAP; t += 512) {
        const float w = s_w[(int)g_adj_edge[t]];
        const unsigned wb = (unsigned)__bfloat16_as_ushort(__float2bfloat16(w));
        g_packed[s][t] = (wb << 16) | (unsigned)g_adj_node[t];
    }
    if (tid < PACK_PAD - ADJ_CAP) g_packed[s][ADJ_CAP + tid] = 0;  // prefetch pad

    // per-node scale: deg (fp32 exact) + 1 + wsl; one thread per sorted slot
    if (tid < N_SLOTS_PAD) {
        const int w = g_order[tid];
        if (w != 0xFFFF) {
            const int beg = g_rowptr4[tid];
            const int end = g_rowptr4[tid + 1];
            float deg = 0.0f;
            for (int t = beg; t < end; ++t)
                deg += s_w[(int)g_adj_edge[t]];     // dummies add 0
            g_sc[s][w] = deg + 1.0f + weight_sl[(size_t)s * N_NODES + w];
        }
    }
}

// ---------------- main kernel: one CTA (512 thr) per batch, occ 4 ----------
// smem = bf16 x tile (26.5 KB) + slot meta copy (20.5 KB) = 47 KB.
// Warp = 4 sorted slots (quarters, equal padded ng); lane covers 8 columns.
// Meta: coalesced L2->smem copy once per CTA, then broadcast LDS.128 per
// group with one-group software prefetch. Inner loop per entry:
// 1 LDS.128 + PRMT + 4 HFMA2 (no deg, no bounds logic).
#define S_XU_B    0
#define S_PACK_B  26496
#define SMEM_BYTES (26496 + PACK_PAD * 4)   // 47008

__device__ __forceinline__ __nv_bfloat162 as_bf2(unsigned v) {
    return *reinterpret_cast<__nv_bfloat162*>(&v);
}
__device__ __forceinline__ unsigned as_u32(__nv_bfloat162 v) {
    return *reinterpret_cast<unsigned*>(&v);
}

#define ENTRY(PK) do {                                                \
    const uint4 u = *(const uint4*)(sxb + ((PK) & 0xffffu));          \
    const __nv_bfloat162 wb = as_bf2(__byte_perm((PK), (PK), 0x3232));\
    c0 = __hfma2(wb, as_bf2(u.x), c0);                                \
    c1 = __hfma2(wb, as_bf2(u.y), c1);                                \
    c2 = __hfma2(wb, as_bf2(u.z), c2);                                \
    c3 = __hfma2(wb, as_bf2(u.w), c3);                                \
} while (0)

__global__ __launch_bounds__(512, 4)
void diffusion_gcn_kernel(const float*  __restrict__ inputs,      // (B,2,N,L)
                          const float*  __restrict__ bias_diff,   // (S,N)
                          const int*    __restrict__ ind,         // (B,)
                          float*        __restrict__ out)         // (B,N,L)
{
    extern __shared__ char smem[];
    unsigned* s_xu   = (unsigned*)(smem + S_XU_B);    // bf16 tile, 32 u32/row
    unsigned* s_pack = (unsigned*)(smem + S_PACK_B);  // slot meta copy

    const int b    = blockIdx.x;
    const int tid  = threadIdx.x;
    const int slot = ind[b];
    const float* __restrict__ xg = inputs + (size_t)b * 2 * N_NODES * LDIM;

    // ---- stage x -> bf16 tile + slot meta -> smem (coalesced both) -------
    {
        const float4* src = (const float4*)xg;
        uint2* dst = (uint2*)s_xu;
        #pragma unroll 4
        for (int i = tid; i < (N_NODES * LDIM) / 4; i += 512) {
            const float4 v = src[i];
            uint2 p;
            p.x = as_u32(__floats2bfloat162_rn(v.x, v.y));
            p.y = as_u32(__floats2bfloat162_rn(v.z, v.w));
            dst[i] = p;
        }
    }
    {
        const uint4* src = (const uint4*)&g_packed[slot][0];
        uint4* dst = (uint4*)s_pack;
        for (int i = tid; i < PACK_PAD / 4; i += 512) dst[i] = __ldg(src + i);
    }
    __syncthreads();

    // ---- gather -----------------------------------------------------------
    const int warp    = tid >> 5;        // 0..15
    const int lane    = tid & 31;
    const int quarter = lane >> 3;       // slot within quad
    const int hl      = lane & 7;        // 8-column group within slot
    const char* sxb   = (const char*)s_xu + 16 * hl;
    const float* scrow = &g_sc[slot][0];
    const float* birow = bias_diff + (size_t)slot * N_NODES;

    #pragma unroll 1
    for (int pass = 0; pass < 4; ++pass) {
        const int sl  = pass * 64 + warp * 4 + quarter;
        const int w   = (int)__ldg(&g_order[sl]);
        const int beg = __ldg(&g_rowptr4[sl]);
        const int ng  = (__ldg(&g_rowptr4[sl + 1]) - beg) >> 2;  // uniform in quad

        const uint4* mp = (const uint4*)(s_pack + beg);
        uint4 p = mp[0];                                          // group 0

        // prefetch diagonal fp32 row chunk (global, L2-hot)
        const float* xr = (w != 0xFFFF) ? (xg + w * LDIM + 8 * hl) : xg;
        const float4 x0 = *(const float4*)xr;

        __nv_bfloat162 c0 = as_bf2(0u), c1 = as_bf2(0u);
        __nv_bfloat162 c2 = as_bf2(0u), c3 = as_bf2(0u);

        #pragma unroll 1
        for (int g = 0; g < ng; ++g) {
            const uint4 pn = mp[g + 1];          // padded over-read is safe
            ENTRY(p.x);
            ENTRY(p.y);
            ENTRY(p.z);
            ENTRY(p.w);
            p = pn;
        }

        if (w != 0xFFFF) {
            const float4 x1 = *(const float4*)(xr + 4);
            const float sc = __ldg(scrow + w);
            const float bi = __ldg(birow + w);
            const unsigned r0 = as_u32(c0), r1 = as_u32(c1);
            const unsigned r2 = as_u32(c2), r3 = as_u32(c3);
            float4 o0, o1;
            o0.x = fmaf(sc, x0.x, bi - __uint_as_float(r0 << 16));
            o0.y = fmaf(sc, x0.y, bi - __uint_as_float(r0 & 0xffff0000u));
            o0.z = fmaf(sc, x0.z, bi - __uint_as_float(r1 << 16));
            o0.w = fmaf(sc, x0.w, bi - __uint_as_float(r1 & 0xffff0000u));
            o1.x = fmaf(sc, x1.x, bi - __uint_as_float(r2 << 16));
            o1.y = fmaf(sc, x1.y, bi - __uint_as_float(r2 & 0xffff0000u));
            o1.z = fmaf(sc, x1.z, bi - __uint_as_float(r3 << 16));
            o1.w = fmaf(sc, x1.w, bi - __uint_as_float(r3 & 0xffff0000u));
            float* op = out + ((size_t)b * N_NODES + w) * LDIM + 8 * hl;
            *(float4*)op = o0;
            *(float4*)(op + 4) = o1;
        }
    }
}

// ---------------- launcher ---------------------------------------------
extern "C" void kernel_launch(void* const* d_in, const int* in_sizes, int n_in,
                              void* d_out, int out_size) {
    const float* inputs      = (const float*)d_in[0];
    const float* weight_diff = (const float*)d_in[1];
    const float* bias_diff   = (const float*)d_in[2];
    const float* weight_sl   = (const float*)d_in[3];
    const int*   ind         = (const int*)d_in[4];
    const int*   edge_i      = (const int*)d_in[5];
    const int*   edge_j      = (const int*)d_in[6];
    float*       out         = (float*)d_out;

    static bool attr_set = false;   // host-side config only, not a work guard
    if (!attr_set) {
        cudaFuncSetAttribute(diffusion_gcn_kernel,
                             cudaFuncAttributeMaxDynamicSharedMemorySize,
                             SMEM_BYTES);
        attr_set = true;
    }

    build_csr_kernel<<<1, 1024>>>(edge_i, edge_j);
    pack_meta_kernel<<<N_SLOTS, 512>>>(weight_diff, weight_sl);
    diffusion_gcn_kernel<<<BATCH, 512, SMEM_BYTES>>>(
        inputs, bias_diff, ind, out);
}